// round 5
// baseline (speedup 1.0000x reference)
#include <cuda_runtime.h>
#include <cuda_bf16.h>
#include <math_constants.h>
#include <limits.h>
#include <stdint.h>

#define NPTS 500000
#define BGR 64
#define DIN 64
#define DH 128
#define DO 128
#define TILE 128

// ---------------- device scratch ----------------
__device__ float g_cc[BGR][DH];
// weight fragments: [kchunk][ntile(16)][lane(32)] -> uint4 {bhi0,bhi1,blo0,blo1}
__device__ uint4 g_W1f[4 * 16 * 32];
__device__ uint4 g_W2f[8 * 16 * 32];

__device__ __forceinline__ void atomicMaxFloat(float* addr, float val) {
    if (val >= 0.0f) atomicMax((int*)addr, __float_as_int(val));
    else             atomicMin((unsigned int*)addr, __float_as_uint(val));
}

__device__ __forceinline__ uint32_t pk_hi(float a, float b) {
    __nv_bfloat162 t = __halves2bfloat162(__float2bfloat16_rn(a), __float2bfloat16_rn(b));
    return *(uint32_t*)&t;
}
__device__ __forceinline__ uint32_t pk_lo(float a, float b) {
    float ra = a - __bfloat162float(__float2bfloat16_rn(a));
    float rb = b - __bfloat162float(__float2bfloat16_rn(b));
    __nv_bfloat162 t = __halves2bfloat162(__float2bfloat16_rn(ra), __float2bfloat16_rn(rb));
    return *(uint32_t*)&t;
}

__device__ __forceinline__ void mma16816(float* c, const uint32_t* a, uint32_t b0, uint32_t b1) {
    asm volatile(
        "mma.sync.aligned.m16n8k16.row.col.f32.bf16.bf16.f32 "
        "{%0,%1,%2,%3}, {%4,%5,%6,%7}, {%8,%9}, {%0,%1,%2,%3};"
        : "+f"(c[0]), "+f"(c[1]), "+f"(c[2]), "+f"(c[3])
        : "r"(a[0]), "r"(a[1]), "r"(a[2]), "r"(a[3]), "r"(b0), "r"(b1));
}

// ---------------- k_prep: out init + weight fragment packing ----------------
__global__ void k_prep(const float* __restrict__ W1, const float* __restrict__ W2,
                       float* out, int out_size) {
    int i = blockIdx.x * blockDim.x + threadIdx.x;   // 4096 threads
    // init segment-max region to -inf
    int lim = (BGR * DO < out_size) ? BGR * DO : out_size;
    for (int j = i; j < lim; j += 4096) out[j] = -CUDART_INF_F;

    if (i < 4 * 16 * 32) {   // W1x fragment: t(4), j(16), l(32)
        int l = i & 31, t = i >> 9;
        int n = 8 * ((i >> 5) & 15) + (l >> 2);
        int k0 = 16 * t + 2 * (l & 3);
        float w00 = W1[(DIN + k0) * DH + n];
        float w01 = W1[(DIN + k0 + 1) * DH + n];
        float w10 = W1[(DIN + k0 + 8) * DH + n];
        float w11 = W1[(DIN + k0 + 9) * DH + n];
        uint4 v;
        v.x = pk_hi(w00, w01); v.y = pk_hi(w10, w11);
        v.z = pk_lo(w00, w01); v.w = pk_lo(w10, w11);
        g_W1f[i] = v;
    }
    if (i < 8 * 16 * 32) {   // W2 fragment: t(8), j(16), l(32)
        int l = i & 31, t = i >> 9;
        int n = 8 * ((i >> 5) & 15) + (l >> 2);
        int k0 = 16 * t + 2 * (l & 3);
        float w00 = W2[k0 * DO + n];
        float w01 = W2[(k0 + 1) * DO + n];
        float w10 = W2[(k0 + 8) * DO + n];
        float w11 = W2[(k0 + 9) * DO + n];
        uint4 v;
        v.x = pk_hi(w00, w01); v.y = pk_hi(w10, w11);
        v.z = pk_lo(w00, w01); v.w = pk_lo(w10, w11);
        g_W2f[i] = v;
    }
}

// ---------------- k_graph: per-graph COM + argmin + c_g + small outputs ----
__global__ __launch_bounds__(256) void k_graph(
    const float* __restrict__ x, const float* __restrict__ pos,
    const int* __restrict__ batch, const float* __restrict__ lf,
    const float* __restrict__ W1, const float* __restrict__ b1,
    float* out, int out_size) {

    __shared__ int s_s, s_e;
    __shared__ float s_red[3][8];
    __shared__ float s_com[3];
    __shared__ unsigned long long s_best;
    __shared__ int s_idx;
    __shared__ float s_x[DIN];
    __shared__ float s_p[3];

    const int g = blockIdx.x;
    const int tid = threadIdx.x;
    const int wid = tid >> 5, l = tid & 31;

    if (tid == 0) {
        int lo = 0, hi = NPTS;
        while (lo < hi) { int m = (lo + hi) >> 1; if (batch[m] < g) lo = m + 1; else hi = m; }
        s_s = lo;
        hi = NPTS;
        while (lo < hi) { int m = (lo + hi) >> 1; if (batch[m] <= g) lo = m + 1; else hi = m; }
        s_e = lo;
        s_best = ~0ull;
    }
    __syncthreads();
    const int s = s_s, e = s_e;

    // ---- phase A: COM ----
    float sx = 0.f, sy = 0.f, sz = 0.f;
    for (int i = s + tid; i < e; i += 256) {
        sx += pos[3 * i]; sy += pos[3 * i + 1]; sz += pos[3 * i + 2];
    }
    #pragma unroll
    for (int d = 16; d >= 1; d >>= 1) {
        sx += __shfl_xor_sync(0xffffffffu, sx, d);
        sy += __shfl_xor_sync(0xffffffffu, sy, d);
        sz += __shfl_xor_sync(0xffffffffu, sz, d);
    }
    if (l == 0) { s_red[0][wid] = sx; s_red[1][wid] = sy; s_red[2][wid] = sz; }
    __syncthreads();
    if (tid < 3) {
        float t = 0.f;
        #pragma unroll
        for (int w = 0; w < 8; w++) t += s_red[tid][w];
        float cnt = (float)(e - s);
        s_com[tid] = t / fmaxf(cnt, 1.0f);
    }
    __syncthreads();

    // ---- phase B: argmin dist (first occurrence) ----
    {
        const float cx = s_com[0], cy = s_com[1], cz = s_com[2];
        unsigned long long best = ~0ull;
        for (int i = s + tid; i < e; i += 256) {
            float dx = pos[3 * i] - cx, dy = pos[3 * i + 1] - cy, dz = pos[3 * i + 2] - cz;
            float d = sqrtf(dx * dx + dy * dy + dz * dz);
            unsigned long long key = ((unsigned long long)__float_as_uint(d) << 32) | (unsigned)i;
            if (key < best) best = key;
        }
        atomicMin(&s_best, best);
    }
    __syncthreads();
    if (tid == 0)
        s_idx = (e > s) ? (int)(unsigned)(s_best & 0xffffffffu) : (NPTS - 1);
    __syncthreads();
    const int idx = s_idx;
    if (tid < DIN) s_x[tid] = x[(size_t)idx * DIN + tid];
    if (tid < 3) s_p[tid] = pos[3 * idx + tid];
    __syncthreads();

    // ---- phase C: c_g + small outputs ----
    if (tid < DH) {
        int j = tid;
        float c = b1[j];
        #pragma unroll 8
        for (int k = 0; k < DIN; k++)
            c += s_x[k] * (W1[k * DH + j] - W1[(DIN + k) * DH + j]);
        c -= s_p[0] * W1[(2 * DIN) * DH + j] + s_p[1] * W1[(2 * DIN + 1) * DH + j]
           + s_p[2] * W1[(2 * DIN + 2) * DH + j];
        g_cc[g][j] = c;
        if (j < 3)  { int o = BGR * DO + g * 3 + j;               if (o < out_size) out[o] = s_p[j]; }
        if (j == 0) { int o = BGR * DO + BGR * 3 + g;             if (o < out_size) out[o] = (float)g; }
        if (j < 9)  { int o = BGR * DO + BGR * 3 + BGR + g*9 + j; if (o < out_size) out[o] = lf[(size_t)idx * 9 + j]; }
    }
}

// ---------------- main fused mma.sync kernel (2 CTAs/SM) ----------------
__global__ void __launch_bounds__(256, 2) k_main(
    const float* __restrict__ x, const float* __restrict__ pos,
    const int* __restrict__ batch, const float* __restrict__ W1,
    const float* __restrict__ b2, float* __restrict__ out) {

    __shared__ float wpx[128], wpy[128], wpz[128];
    __shared__ float cgs[128], b2s[128];
    __shared__ float px[128], py[128], pz[128];
    __shared__ float red[8 * 128];
    __shared__ int gbs[128];

    const int tid = threadIdx.x;
    const int wid = tid >> 5, l = tid & 31;
    const int row0 = blockIdx.x * TILE;

    if (tid < 128) {
        wpx[tid] = W1[(2 * DIN + 0) * DH + tid];
        wpy[tid] = W1[(2 * DIN + 1) * DH + tid];
        wpz[tid] = W1[(2 * DIN + 2) * DH + tid];
        b2s[tid] = b2[tid];
        int row = row0 + tid;
        if (row < NPTS) {
            px[tid] = pos[3 * row]; py[tid] = pos[3 * row + 1]; pz[tid] = pos[3 * row + 2];
            gbs[tid] = batch[row];
        } else {
            px[tid] = py[tid] = pz[tid] = 0.f;
            gbs[tid] = -1;
        }
    }
    __syncthreads();
    const int gu = gbs[0];
    const bool uni = (gu >= 0) && (gu == gbs[127]);
    if (tid < 128) cgs[tid] = (gu >= 0) ? g_cc[gu][tid] : 0.f;
    __syncthreads();

    const int rr0 = wid * 16 + (l >> 2);
    const int rr1 = rr0 + 8;
    const int r0 = row0 + rr0, r1 = row0 + rr1;
    const int m4 = 2 * (l & 3);

    // ---------- load x fragments once (kept resident) ----------
    uint32_t xhi[4][4], xlo[4][4];
    #pragma unroll
    for (int t = 0; t < 4; t++) {
        const int kb = 16 * t + m4;
        float2 x00 = make_float2(0.f, 0.f), x01 = x00, x10 = x00, x11 = x00;
        if (r0 < NPTS) {
            x00 = *(const float2*)(x + (size_t)r0 * DIN + kb);
            x01 = *(const float2*)(x + (size_t)r0 * DIN + kb + 8);
        }
        if (r1 < NPTS) {
            x10 = *(const float2*)(x + (size_t)r1 * DIN + kb);
            x11 = *(const float2*)(x + (size_t)r1 * DIN + kb + 8);
        }
        xhi[t][0] = pk_hi(x00.x, x00.y); xhi[t][1] = pk_hi(x10.x, x10.y);
        xhi[t][2] = pk_hi(x01.x, x01.y); xhi[t][3] = pk_hi(x11.x, x11.y);
        xlo[t][0] = pk_lo(x00.x, x00.y); xlo[t][1] = pk_lo(x10.x, x10.y);
        xlo[t][2] = pk_lo(x01.x, x01.y); xlo[t][3] = pk_lo(x11.x, x11.y);
    }

    const float p0x = px[rr0], p0y = py[rr0], p0z = pz[rr0];
    const float p1x = px[rr1], p1y = py[rr1], p1z = pz[rr1];
    const int g0 = gbs[rr0], g1 = gbs[rr1];

    // ---------- phase 1: two 64-col halves; term-separated j-sweeps ----------
    uint32_t ahi[16][2], alo[16][2];
    #pragma unroll
    for (int h = 0; h < 2; h++) {
        float acc1[8][4];
        #pragma unroll
        for (int j = 0; j < 8; j++)
            #pragma unroll
            for (int q = 0; q < 4; q++) acc1[j][q] = 0.f;

        #pragma unroll
        for (int t = 0; t < 4; t++) {
            const uint4* wf = g_W1f + (t * 16 + h * 8) * 32 + l;
            uint4 B[8];
            #pragma unroll
            for (int j = 0; j < 8; j++) B[j] = wf[j * 32];
            #pragma unroll
            for (int j = 0; j < 8; j++) mma16816(acc1[j], xhi[t], B[j].x, B[j].y);
            #pragma unroll
            for (int j = 0; j < 8; j++) mma16816(acc1[j], xhi[t], B[j].z, B[j].w);
            #pragma unroll
            for (int j = 0; j < 8; j++) mma16816(acc1[j], xlo[t], B[j].x, B[j].y);
        }

        // epilogue 1: + pos*Wp + c_g, relu, split -> A-frags
        #pragma unroll
        for (int j = 0; j < 8; j++) {
            int jj = h * 8 + j;
            int c0 = 8 * jj + m4;
            float2 wx = *(float2*)&wpx[c0];
            float2 wy = *(float2*)&wpy[c0];
            float2 wz = *(float2*)&wpz[c0];
            float2 cv0, cv1;
            if (uni) {
                cv0 = *(float2*)&cgs[c0]; cv1 = cv0;
            } else {
                cv0 = (g0 >= 0) ? *(const float2*)&g_cc[g0][c0] : make_float2(0.f, 0.f);
                cv1 = (g1 >= 0) ? *(const float2*)&g_cc[g1][c0] : make_float2(0.f, 0.f);
            }
            float v0 = fmaxf(acc1[j][0] + p0x * wx.x + p0y * wy.x + p0z * wz.x + cv0.x, 0.f);
            float v1 = fmaxf(acc1[j][1] + p0x * wx.y + p0y * wy.y + p0z * wz.y + cv0.y, 0.f);
            float v2 = fmaxf(acc1[j][2] + p1x * wx.x + p1y * wy.x + p1z * wz.x + cv1.x, 0.f);
            float v3 = fmaxf(acc1[j][3] + p1x * wx.y + p1y * wy.y + p1z * wz.y + cv1.y, 0.f);
            ahi[jj][0] = pk_hi(v0, v1); ahi[jj][1] = pk_hi(v2, v3);
            alo[jj][0] = pk_lo(v0, v1); alo[jj][1] = pk_lo(v2, v3);
        }
    }

    // ---------- phase 2: two 64-col halves; groups of 4 j, term-separated ----
    #pragma unroll
    for (int h = 0; h < 2; h++) {
        float acc2[8][4];
        #pragma unroll
        for (int j = 0; j < 8; j++)
            #pragma unroll
            for (int q = 0; q < 4; q++) acc2[j][q] = 0.f;

        #pragma unroll
        for (int t = 0; t < 8; t++) {
            uint32_t Ahi[4] = { ahi[2 * t][0], ahi[2 * t][1], ahi[2 * t + 1][0], ahi[2 * t + 1][1] };
            uint32_t Alo[4] = { alo[2 * t][0], alo[2 * t][1], alo[2 * t + 1][0], alo[2 * t + 1][1] };
            const uint4* wf = g_W2f + (t * 16 + h * 8) * 32 + l;
            #pragma unroll
            for (int jg = 0; jg < 2; jg++) {
                uint4 B[4];
                #pragma unroll
                for (int j = 0; j < 4; j++) B[j] = wf[(jg * 4 + j) * 32];
                #pragma unroll
                for (int j = 0; j < 4; j++) mma16816(acc2[jg * 4 + j], Ahi, B[j].x, B[j].y);
                #pragma unroll
                for (int j = 0; j < 4; j++) mma16816(acc2[jg * 4 + j], Ahi, B[j].z, B[j].w);
                #pragma unroll
                for (int j = 0; j < 4; j++) mma16816(acc2[jg * 4 + j], Alo, B[j].x, B[j].y);
            }
        }

        // epilogue 2
        if (uni) {
            #pragma unroll
            for (int j = 0; j < 8; j++) {
                int c0 = 8 * (h * 8 + j) + m4;
                float m0 = fmaxf(acc2[j][0], acc2[j][2]);
                float m1 = fmaxf(acc2[j][1], acc2[j][3]);
                #pragma unroll
                for (int d = 4; d < 32; d <<= 1) {
                    m0 = fmaxf(m0, __shfl_xor_sync(0xffffffffu, m0, d));
                    m1 = fmaxf(m1, __shfl_xor_sync(0xffffffffu, m1, d));
                }
                if (l < 4) {
                    red[wid * 128 + c0] = m0;
                    red[wid * 128 + c0 + 1] = m1;
                }
            }
        } else {
            #pragma unroll
            for (int j = 0; j < 8; j++) {
                int c0 = 8 * (h * 8 + j) + m4;
                if (g0 >= 0) {
                    atomicMaxFloat(&out[g0 * DO + c0],     acc2[j][0] + b2s[c0]);
                    atomicMaxFloat(&out[g0 * DO + c0 + 1], acc2[j][1] + b2s[c0 + 1]);
                }
                if (g1 >= 0) {
                    atomicMaxFloat(&out[g1 * DO + c0],     acc2[j][2] + b2s[c0]);
                    atomicMaxFloat(&out[g1 * DO + c0 + 1], acc2[j][3] + b2s[c0 + 1]);
                }
            }
        }
    }

    if (uni) {
        __syncthreads();
        if (tid < 128) {
            float m = red[tid];
            #pragma unroll
            for (int w = 1; w < 8; w++) m = fmaxf(m, red[w * 128 + tid]);
            atomicMaxFloat(&out[gu * DO + tid], m + b2s[tid]);
        }
    }
}

// ---------------- launch ----------------
extern "C" void kernel_launch(void* const* d_in, const int* in_sizes, int n_in,
                              void* d_out, int out_size) {
    const float* x     = (const float*)d_in[0];
    const float* pos   = (const float*)d_in[1];
    const int*   batch = (const int*)d_in[2];
    const float* lf    = (const float*)d_in[3];
    const float* W1    = (const float*)d_in[4];
    const float* b1    = (const float*)d_in[5];
    const float* W2    = (const float*)d_in[6];
    const float* b2    = (const float*)d_in[7];
    float* out = (float*)d_out;

    k_prep<<<16, 256>>>(W1, W2, out, out_size);
    k_graph<<<BGR, 256>>>(x, pos, batch, lf, W1, b1, out, out_size);
    int grid = (NPTS + TILE - 1) / TILE;
    k_main<<<grid, 256>>>(x, pos, batch, W1, b2, out);
}

// round 6
// speedup vs baseline: 1.8807x; 1.8807x over previous
#include <cuda_runtime.h>
#include <cuda_fp16.h>
#include <math_constants.h>
#include <limits.h>
#include <stdint.h>

#define NPTS 500000
#define BGR 64
#define DIN 64
#define DH 128
#define DO 128
#define TILE 128

// ---------------- device scratch ----------------
__device__ float g_cc[BGR][DH];
// fp16 weight fragments: [kchunk][ntile(16)][lane(32)] -> uint2 {b0,b1}
__device__ uint2 g_W1f[4 * 16 * 32];
__device__ uint2 g_W2f[8 * 16 * 32];

__device__ __forceinline__ void atomicMaxFloat(float* addr, float val) {
    if (val >= 0.0f) atomicMax((int*)addr, __float_as_int(val));
    else             atomicMin((unsigned int*)addr, __float_as_uint(val));
}

__device__ __forceinline__ uint32_t pk16(float a, float b) {
    __half2 t = __halves2half2(__float2half_rn(a), __float2half_rn(b));
    return *(uint32_t*)&t;
}

__device__ __forceinline__ void mma16816(float* c, const uint32_t* a, uint32_t b0, uint32_t b1) {
    asm volatile(
        "mma.sync.aligned.m16n8k16.row.col.f32.f16.f16.f32 "
        "{%0,%1,%2,%3}, {%4,%5,%6,%7}, {%8,%9}, {%0,%1,%2,%3};"
        : "+f"(c[0]), "+f"(c[1]), "+f"(c[2]), "+f"(c[3])
        : "r"(a[0]), "r"(a[1]), "r"(a[2]), "r"(a[3]), "r"(b0), "r"(b1));
}

// ---------------- k_prep: out init + weight fragment packing ----------------
__global__ void k_prep(const float* __restrict__ W1, const float* __restrict__ W2,
                       float* out, int out_size) {
    int i = blockIdx.x * blockDim.x + threadIdx.x;   // 4096 threads
    int lim = (BGR * DO < out_size) ? BGR * DO : out_size;
    for (int j = i; j < lim; j += 4096) out[j] = -CUDART_INF_F;

    if (i < 4 * 16 * 32) {   // W1x fragment: t(4), j(16), l(32)
        int l = i & 31, t = i >> 9;
        int n = 8 * ((i >> 5) & 15) + (l >> 2);
        int k0 = 16 * t + 2 * (l & 3);
        uint2 v;
        v.x = pk16(W1[(DIN + k0) * DH + n],     W1[(DIN + k0 + 1) * DH + n]);
        v.y = pk16(W1[(DIN + k0 + 8) * DH + n], W1[(DIN + k0 + 9) * DH + n]);
        g_W1f[i] = v;
    }
    if (i < 8 * 16 * 32) {   // W2 fragment: t(8), j(16), l(32)
        int l = i & 31, t = i >> 9;
        int n = 8 * ((i >> 5) & 15) + (l >> 2);
        int k0 = 16 * t + 2 * (l & 3);
        uint2 v;
        v.x = pk16(W2[k0 * DO + n],       W2[(k0 + 1) * DO + n]);
        v.y = pk16(W2[(k0 + 8) * DO + n], W2[(k0 + 9) * DO + n]);
        g_W2f[i] = v;
    }
}

// ---------------- k_graph: per-graph COM + argmin + c_g + small outputs ----
__global__ __launch_bounds__(256) void k_graph(
    const float* __restrict__ x, const float* __restrict__ pos,
    const int* __restrict__ batch, const float* __restrict__ lf,
    const float* __restrict__ W1, const float* __restrict__ b1,
    float* out, int out_size) {

    __shared__ int s_s, s_e;
    __shared__ float s_red[3][8];
    __shared__ float s_com[3];
    __shared__ unsigned long long s_best;
    __shared__ int s_idx;
    __shared__ float s_x[DIN];
    __shared__ float s_p[3];

    const int g = blockIdx.x;
    const int tid = threadIdx.x;
    const int wid = tid >> 5, l = tid & 31;

    if (tid == 0) {
        int lo = 0, hi = NPTS;
        while (lo < hi) { int m = (lo + hi) >> 1; if (batch[m] < g) lo = m + 1; else hi = m; }
        s_s = lo;
        hi = NPTS;
        while (lo < hi) { int m = (lo + hi) >> 1; if (batch[m] <= g) lo = m + 1; else hi = m; }
        s_e = lo;
        s_best = ~0ull;
    }
    __syncthreads();
    const int s = s_s, e = s_e;

    // ---- phase A: COM ----
    float sx = 0.f, sy = 0.f, sz = 0.f;
    for (int i = s + tid; i < e; i += 256) {
        sx += pos[3 * i]; sy += pos[3 * i + 1]; sz += pos[3 * i + 2];
    }
    #pragma unroll
    for (int d = 16; d >= 1; d >>= 1) {
        sx += __shfl_xor_sync(0xffffffffu, sx, d);
        sy += __shfl_xor_sync(0xffffffffu, sy, d);
        sz += __shfl_xor_sync(0xffffffffu, sz, d);
    }
    if (l == 0) { s_red[0][wid] = sx; s_red[1][wid] = sy; s_red[2][wid] = sz; }
    __syncthreads();
    if (tid < 3) {
        float t = 0.f;
        #pragma unroll
        for (int w = 0; w < 8; w++) t += s_red[tid][w];
        float cnt = (float)(e - s);
        s_com[tid] = t / fmaxf(cnt, 1.0f);
    }
    __syncthreads();

    // ---- phase B: argmin dist (first occurrence) ----
    {
        const float cx = s_com[0], cy = s_com[1], cz = s_com[2];
        unsigned long long best = ~0ull;
        for (int i = s + tid; i < e; i += 256) {
            float dx = pos[3 * i] - cx, dy = pos[3 * i + 1] - cy, dz = pos[3 * i + 2] - cz;
            float d = sqrtf(dx * dx + dy * dy + dz * dz);
            unsigned long long key = ((unsigned long long)__float_as_uint(d) << 32) | (unsigned)i;
            if (key < best) best = key;
        }
        atomicMin(&s_best, best);
    }
    __syncthreads();
    if (tid == 0)
        s_idx = (e > s) ? (int)(unsigned)(s_best & 0xffffffffu) : (NPTS - 1);
    __syncthreads();
    const int idx = s_idx;
    if (tid < DIN) s_x[tid] = x[(size_t)idx * DIN + tid];
    if (tid < 3) s_p[tid] = pos[3 * idx + tid];
    __syncthreads();

    // ---- phase C: c_g + small outputs ----
    if (tid < DH) {
        int j = tid;
        float c = b1[j];
        #pragma unroll 8
        for (int k = 0; k < DIN; k++)
            c += s_x[k] * (W1[k * DH + j] - W1[(DIN + k) * DH + j]);
        c -= s_p[0] * W1[(2 * DIN) * DH + j] + s_p[1] * W1[(2 * DIN + 1) * DH + j]
           + s_p[2] * W1[(2 * DIN + 2) * DH + j];
        g_cc[g][j] = c;
        if (j < 3)  { int o = BGR * DO + g * 3 + j;               if (o < out_size) out[o] = s_p[j]; }
        if (j == 0) { int o = BGR * DO + BGR * 3 + g;             if (o < out_size) out[o] = (float)g; }
        if (j < 9)  { int o = BGR * DO + BGR * 3 + BGR + g*9 + j; if (o < out_size) out[o] = lf[(size_t)idx * 9 + j]; }
    }
}

// ---------------- main fused mma.sync kernel (fp16 single-pass) ----------------
__global__ void __launch_bounds__(256, 2) k_main(
    const float* __restrict__ x, const float* __restrict__ pos,
    const int* __restrict__ batch, const float* __restrict__ W1,
    const float* __restrict__ b2, float* __restrict__ out) {

    __shared__ float wpx[128], wpy[128], wpz[128];
    __shared__ float cgs[128], b2s[128];
    __shared__ float px[128], py[128], pz[128];
    __shared__ float red[8 * 128];
    __shared__ int gbs[128];

    const int tid = threadIdx.x;
    const int wid = tid >> 5, l = tid & 31;
    const int row0 = blockIdx.x * TILE;

    if (tid < 128) {
        wpx[tid] = W1[(2 * DIN + 0) * DH + tid];
        wpy[tid] = W1[(2 * DIN + 1) * DH + tid];
        wpz[tid] = W1[(2 * DIN + 2) * DH + tid];
        b2s[tid] = b2[tid];
        int row = row0 + tid;
        if (row < NPTS) {
            px[tid] = pos[3 * row]; py[tid] = pos[3 * row + 1]; pz[tid] = pos[3 * row + 2];
            gbs[tid] = batch[row];
        } else {
            px[tid] = py[tid] = pz[tid] = 0.f;
            gbs[tid] = -1;
        }
    }
    __syncthreads();
    const int gu = gbs[0];
    const bool uni = (gu >= 0) && (gu == gbs[127]);
    if (tid < 128) cgs[tid] = (gu >= 0) ? g_cc[gu][tid] : 0.f;
    __syncthreads();

    const int rr0 = wid * 16 + (l >> 2);
    const int rr1 = rr0 + 8;
    const int r0 = row0 + rr0, r1 = row0 + rr1;
    const int m4 = 2 * (l & 3);

    // ---------- load x fragments once (fp16, kept resident) ----------
    uint32_t xh[4][4];
    #pragma unroll
    for (int t = 0; t < 4; t++) {
        const int kb = 16 * t + m4;
        float2 x00 = make_float2(0.f, 0.f), x01 = x00, x10 = x00, x11 = x00;
        if (r0 < NPTS) {
            x00 = *(const float2*)(x + (size_t)r0 * DIN + kb);
            x01 = *(const float2*)(x + (size_t)r0 * DIN + kb + 8);
        }
        if (r1 < NPTS) {
            x10 = *(const float2*)(x + (size_t)r1 * DIN + kb);
            x11 = *(const float2*)(x + (size_t)r1 * DIN + kb + 8);
        }
        xh[t][0] = pk16(x00.x, x00.y); xh[t][1] = pk16(x10.x, x10.y);
        xh[t][2] = pk16(x01.x, x01.y); xh[t][3] = pk16(x11.x, x11.y);
    }

    const float p0x = px[rr0], p0y = py[rr0], p0z = pz[rr0];
    const float p1x = px[rr1], p1y = py[rr1], p1z = pz[rr1];
    const int g0 = gbs[rr0], g1 = gbs[rr1];

    // ---------- phase 1: two 64-col halves ----------
    uint32_t ah[16][2];
    #pragma unroll
    for (int h = 0; h < 2; h++) {
        float acc1[8][4];
        #pragma unroll
        for (int j = 0; j < 8; j++)
            #pragma unroll
            for (int q = 0; q < 4; q++) acc1[j][q] = 0.f;

        #pragma unroll
        for (int t = 0; t < 4; t++) {
            const uint2* wf = g_W1f + (t * 16 + h * 8) * 32 + l;
            uint2 B[8];
            #pragma unroll
            for (int j = 0; j < 8; j++) B[j] = wf[j * 32];
            #pragma unroll
            for (int j = 0; j < 8; j++) mma16816(acc1[j], xh[t], B[j].x, B[j].y);
        }

        // epilogue 1: + pos*Wp + c_g, relu -> fp16 A-frags
        #pragma unroll
        for (int j = 0; j < 8; j++) {
            int jj = h * 8 + j;
            int c0 = 8 * jj + m4;
            float2 wx = *(float2*)&wpx[c0];
            float2 wy = *(float2*)&wpy[c0];
            float2 wz = *(float2*)&wpz[c0];
            float2 cv0, cv1;
            if (uni) {
                cv0 = *(float2*)&cgs[c0]; cv1 = cv0;
            } else {
                cv0 = (g0 >= 0) ? *(const float2*)&g_cc[g0][c0] : make_float2(0.f, 0.f);
                cv1 = (g1 >= 0) ? *(const float2*)&g_cc[g1][c0] : make_float2(0.f, 0.f);
            }
            float v0 = fmaxf(acc1[j][0] + p0x * wx.x + p0y * wy.x + p0z * wz.x + cv0.x, 0.f);
            float v1 = fmaxf(acc1[j][1] + p0x * wx.y + p0y * wy.y + p0z * wz.y + cv0.y, 0.f);
            float v2 = fmaxf(acc1[j][2] + p1x * wx.x + p1y * wy.x + p1z * wz.x + cv1.x, 0.f);
            float v3 = fmaxf(acc1[j][3] + p1x * wx.y + p1y * wy.y + p1z * wz.y + cv1.y, 0.f);
            ah[jj][0] = pk16(v0, v1); ah[jj][1] = pk16(v2, v3);
        }
    }

    // ---------- phase 2: two 64-col halves ----------
    #pragma unroll
    for (int h = 0; h < 2; h++) {
        float acc2[8][4];
        #pragma unroll
        for (int j = 0; j < 8; j++)
            #pragma unroll
            for (int q = 0; q < 4; q++) acc2[j][q] = 0.f;

        #pragma unroll
        for (int t = 0; t < 8; t++) {
            uint32_t A[4] = { ah[2 * t][0], ah[2 * t][1], ah[2 * t + 1][0], ah[2 * t + 1][1] };
            const uint2* wf = g_W2f + (t * 16 + h * 8) * 32 + l;
            uint2 B[8];
            #pragma unroll
            for (int j = 0; j < 8; j++) B[j] = wf[j * 32];
            #pragma unroll
            for (int j = 0; j < 8; j++) mma16816(acc2[j], A, B[j].x, B[j].y);
        }

        // epilogue 2
        if (uni) {
            #pragma unroll
            for (int j = 0; j < 8; j++) {
                int c0 = 8 * (h * 8 + j) + m4;
                float m0 = fmaxf(acc2[j][0], acc2[j][2]);
                float m1 = fmaxf(acc2[j][1], acc2[j][3]);
                #pragma unroll
                for (int d = 4; d < 32; d <<= 1) {
                    m0 = fmaxf(m0, __shfl_xor_sync(0xffffffffu, m0, d));
                    m1 = fmaxf(m1, __shfl_xor_sync(0xffffffffu, m1, d));
                }
                if (l < 4) {
                    red[wid * 128 + c0] = m0;
                    red[wid * 128 + c0 + 1] = m1;
                }
            }
        } else {
            #pragma unroll
            for (int j = 0; j < 8; j++) {
                int c0 = 8 * (h * 8 + j) + m4;
                if (g0 >= 0) {
                    atomicMaxFloat(&out[g0 * DO + c0],     acc2[j][0] + b2s[c0]);
                    atomicMaxFloat(&out[g0 * DO + c0 + 1], acc2[j][1] + b2s[c0 + 1]);
                }
                if (g1 >= 0) {
                    atomicMaxFloat(&out[g1 * DO + c0],     acc2[j][2] + b2s[c0]);
                    atomicMaxFloat(&out[g1 * DO + c0 + 1], acc2[j][3] + b2s[c0 + 1]);
                }
            }
        }
    }

    if (uni) {
        __syncthreads();
        if (tid < 128) {
            float m = red[tid];
            #pragma unroll
            for (int w = 1; w < 8; w++) m = fmaxf(m, red[w * 128 + tid]);
            atomicMaxFloat(&out[gu * DO + tid], m + b2s[tid]);
        }
    }
}

// ---------------- launch ----------------
extern "C" void kernel_launch(void* const* d_in, const int* in_sizes, int n_in,
                              void* d_out, int out_size) {
    const float* x     = (const float*)d_in[0];
    const float* pos   = (const float*)d_in[1];
    const int*   batch = (const int*)d_in[2];
    const float* lf    = (const float*)d_in[3];
    const float* W1    = (const float*)d_in[4];
    const float* b1    = (const float*)d_in[5];
    const float* W2    = (const float*)d_in[6];
    const float* b2    = (const float*)d_in[7];
    float* out = (float*)d_out;

    k_prep<<<16, 256>>>(W1, W2, out, out_size);
    k_graph<<<BGR, 256>>>(x, pos, batch, lf, W1, b1, out, out_size);
    int grid = (NPTS + TILE - 1) / TILE;
    k_main<<<grid, 256>>>(x, pos, batch, W1, b2, out);
}